// round 11
// baseline (speedup 1.0000x reference)
#include <cuda_runtime.h>

#define NRELS 19
#define CPAD  20
#define DIM   32
#define MAXN  100000
#define MAXE  1600000

typedef unsigned int u32;

// ---------------- static scratch (no allocation; zero-init; each consumer
// kernel resets what it read, so every graph replay starts pristine) --------
static __device__ int4   g_cnt4[MAXN * (CPAD / 4)];   // (node,rel) counts
static __device__ float4 g_h14[MAXN * (DIM / 4)];     // layer-1 activations
static __device__ float4 g_h2[MAXN * (DIM / 4)];      // layer-2 accumulator (perm cols)
static __device__ int2   g_edata[MAXE];               // relation-bucketed (src,dst)
static __device__ int    g_relHist[NRELS];
static __device__ int    g_relCur[NRELS];

// ---------------- helpers ----------------
__device__ __forceinline__ void red4(float* p, float a, float b, float c, float d) {
    asm volatile("red.global.add.v4.f32 [%0], {%1, %2, %3, %4};"
                 :: "l"(p), "f"(a), "f"(b), "f"(c), "f"(d) : "memory");
}
__device__ __forceinline__ u32 smem_u32(const void* p) {
    return (u32)__cvta_generic_to_shared(p);
}
__device__ __forceinline__ void cp_async16(u32 dst, const void* src, int srcsize) {
    asm volatile("cp.async.cg.shared.global [%0], [%1], 16, %2;"
                 :: "r"(dst), "l"(src), "r"(srcsize));
}
__device__ __forceinline__ void cp_commit() { asm volatile("cp.async.commit_group;"); }
__device__ __forceinline__ void cp_wait1()  { asm volatile("cp.async.wait_group 1;"); }
__device__ __forceinline__ void cp_wait0()  { asm volatile("cp.async.wait_group 0;"); }
__device__ __forceinline__ u32 cvt_tf32(float x) {
    u32 r; asm("cvt.rna.tf32.f32 %0, %1;" : "=r"(r) : "f"(x)); return r;
}
// m16n8k8 tf32 MMA, D=C accumulate in place.
__device__ __forceinline__ void mma_tf32(float& c0, float& c1, float& c2, float& c3,
                                         u32 a0, u32 a1, u32 a2, u32 a3,
                                         u32 b0, u32 b1) {
    asm volatile("mma.sync.aligned.m16n8k8.row.col.f32.tf32.tf32.f32 "
                 "{%0,%1,%2,%3}, {%4,%5,%6,%7}, {%8,%9}, {%0,%1,%2,%3};"
                 : "+f"(c0), "+f"(c1), "+f"(c2), "+f"(c3)
                 : "r"(a0), "r"(a1), "r"(a2), "r"(a3), "r"(b0), "r"(b1));
}

// ---------------- kernels (order: hist, scatter, layer1, LAYER2, final) ----

// Per-(dst,rel) counts + relation histogram.  cnt/relHist start zero
// (zero-init first call; reset by k_layer1/k_final on every pass).
__global__ void k_hist(const int* __restrict__ dst, const int* __restrict__ et, int E) {
    __shared__ int sh[NRELS];
    if (threadIdx.x < NRELS) sh[threadIdx.x] = 0;
    __syncthreads();
    int* cnt = (int*)g_cnt4;
    int e0 = (blockIdx.x * blockDim.x + threadIdx.x) * 4;
    if (e0 + 3 < E) {
        int4 d4 = *(const int4*)&dst[e0];
        int4 r4 = *(const int4*)&et[e0];
        atomicAdd(&cnt[d4.x * CPAD + r4.x], 1);
        atomicAdd(&cnt[d4.y * CPAD + r4.y], 1);
        atomicAdd(&cnt[d4.z * CPAD + r4.z], 1);
        atomicAdd(&cnt[d4.w * CPAD + r4.w], 1);
        atomicAdd(&sh[r4.x], 1); atomicAdd(&sh[r4.y], 1);
        atomicAdd(&sh[r4.z], 1); atomicAdd(&sh[r4.w], 1);
    } else {
        for (int e = e0; e < E; e++) {
            int r = et[e];
            atomicAdd(&cnt[dst[e] * CPAD + r], 1);
            atomicAdd(&sh[r], 1);
        }
    }
    __syncthreads();
    if (threadIdx.x < NRELS) atomicAdd(&g_relHist[threadIdx.x], sh[threadIdx.x]);
}

// Counting-sort scatter by relation; local scan of the 19-entry histogram.
__global__ void k_scatter(const int* __restrict__ src, const int* __restrict__ dst,
                          const int* __restrict__ et, int E) {
    __shared__ int sOff[NRELS];
    __shared__ int shCnt[NRELS];
    __shared__ int shBase[NRELS];
    int t = threadIdx.x;
    if (t < NRELS) {
        shCnt[t] = 0;
        int s = 0;
#pragma unroll
        for (int q = 0; q < NRELS; q++) {
            if (q == t) sOff[t] = s;
            s += g_relHist[q];
        }
    }
    __syncthreads();
    int e0 = (blockIdx.x * blockDim.x + t) * 4;
    int r[4], s[4], d[4], lp[4];
    int cnt = 0;
    if (e0 + 3 < E) {
        int4 s4 = *(const int4*)&src[e0];
        int4 d4 = *(const int4*)&dst[e0];
        int4 r4 = *(const int4*)&et[e0];
        s[0]=s4.x; s[1]=s4.y; s[2]=s4.z; s[3]=s4.w;
        d[0]=d4.x; d[1]=d4.y; d[2]=d4.z; d[3]=d4.w;
        r[0]=r4.x; r[1]=r4.y; r[2]=r4.z; r[3]=r4.w;
        cnt = 4;
    } else {
        for (int e = e0; e < E; e++) {
            s[cnt]=src[e]; d[cnt]=dst[e]; r[cnt]=et[e]; cnt++;
        }
    }
    for (int k = 0; k < cnt; k++) lp[k] = atomicAdd(&shCnt[r[k]], 1);
    __syncthreads();
    if (t < NRELS) shBase[t] = sOff[t] + atomicAdd(&g_relCur[t], shCnt[t]);
    __syncthreads();
    for (int k = 0; k < cnt; k++)
        g_edata[shBase[r[k]] + lp[k]] = make_int2(s[k], d[k]);
}

// Layer 1; also RESETS cnt rows to zero after reading (for next replay).
__global__ void k_layer1(const float* __restrict__ W1, const float* __restrict__ b1, int N) {
    __shared__ float sW[NRELS * DIM];
    __shared__ float sb[DIM];
    int t = threadIdx.x;
    for (int i = t; i < NRELS * DIM; i += blockDim.x) sW[i] = W1[i];
    if (t < DIM) sb[t] = b1[t];
    __syncthreads();
    int lane = t & 31;
    int wpb = blockDim.x >> 5;
    float* h1 = (float*)g_h14;
    for (int v = blockIdx.x * wpb + (t >> 5); v < N; v += gridDim.x * wpb) {
        int4* crow = &g_cnt4[v * (CPAD / 4)];
        int c[CPAD];
#pragma unroll
        for (int q = 0; q < CPAD / 4; q++) {
            int4 cc = __ldg(&crow[q]);
            c[q * 4 + 0] = cc.x; c[q * 4 + 1] = cc.y;
            c[q * 4 + 2] = cc.z; c[q * 4 + 3] = cc.w;
        }
        float acc = sb[lane];
#pragma unroll
        for (int r = 0; r < NRELS; r++)
            acc += (float)c[r] * sW[r * DIM + lane];
        h1[v * DIM + lane] = fmaxf(acc, 0.0f);
        if (lane < CPAD / 4) crow[lane] = make_int4(0, 0, 0, 0);   // reset for next pass
    }
}

// Layer 2 (hot): tensor-core tile kernel.  Per warp, 16 edges per tile:
//   D[16 edges x 32 cols] += A[16 x 32] (gathered h1 rows) @ W2[rel] (32x32)
// via mma.sync.m16n8k8 tf32 with 3-term precision split
// (AhiBhi + AhiBlo + AloBhi, error ~1e-6).
//   - A: cp.async16 gather into XOR-swizzled smem (double-buffered), fragments
//     loaded with conflict-free LDS.32; padded edges zero-filled -> exact 0.
//   - B: W2[rel] hi/lo fragments register-resident (64 regs).
//   - C scatter: h2 stored in a fixed column PERMUTATION so each lane's C regs
//     form contiguous 16B groups -> 4 red.global.add.v4 per tile, no transpose.
//     perm: actual col c -> pos ((c&7)>>1)*8 + (c>>3)*2 + (c&1); k_final inverts.
__global__ void __launch_bounds__(128, 3) k_layer2(const float* __restrict__ W2,
                                                   int E, int nWarps) {
    __shared__ float shh[4][2][512];    // [warp][buf][16 rows x 32 floats] 16KB
    __shared__ int sOff[NRELS + 1];
    int t = threadIdx.x;
    if (t == 0) {
        int s = 0;
        for (int q = 0; q < NRELS; q++) { sOff[q] = s; s += g_relHist[q]; }
        sOff[NRELS] = s;
    }
    __syncthreads();
    int lane = t & 31;
    int warp = t >> 5;
    int gr   = lane >> 2;      // fragment group row (0..7)
    int tig  = lane & 3;       // thread-in-group
    int grow = lane >> 3;      // gather row-in-quad (0..3)
    int gchk = lane & 7;       // gather chunk (16B unit within 128B row)
    u32 shW = smem_u32(&shh[warp][0][0]);   // buf stride 2048 bytes
    const char* sbase = (const char*)&shh[warp][0][0];

    int gw = blockIdx.x * 4 + warp;
    if (gw >= nWarps) return;
    int e    = (int)(((long long)gw * E) / nWarps);
    int eEnd = (int)(((long long)(gw + 1) * E) / nWarps);

    int r = 0;
    while (e < eEnd) {
        while (sOff[r + 1] <= e) r++;
        int runEnd = min(eEnd, sOff[r + 1]);
        if (e >= runEnd) continue;

        // ---- W2[r] fragments (hi/lo tf32 split), register-resident ----
        const float* Wr = W2 + r * DIM * DIM;
        u32 bhi[4][4][2], blo[4][4][2];   // [kb][nb][{k, k+4}]
#pragma unroll
        for (int kb = 0; kb < 4; kb++)
#pragma unroll
            for (int nb = 0; nb < 4; nb++) {
                int k0 = kb * 8 + tig, n0 = nb * 8 + gr;
                float w0 = __ldg(&Wr[k0 * DIM + n0]);
                float w1 = __ldg(&Wr[(k0 + 4) * DIM + n0]);
                u32 h0 = cvt_tf32(w0), h1 = cvt_tf32(w1);
                bhi[kb][nb][0] = h0;
                bhi[kb][nb][1] = h1;
                blo[kb][nb][0] = cvt_tf32(w0 - __uint_as_float(h0));
                blo[kb][nb][1] = cvt_tf32(w1 - __uint_as_float(h1));
            }

        cp_wait0();
        __syncwarp();

        // ---- prolog: edata 2 tiles deep; gather tile 0 into buf 0 ----
        int2 edc = make_int2(0, 0), edn = make_int2(0, 0);
        if (lane < 16 && e + lane < runEnd) edc = __ldg(&g_edata[e + lane]);
        if (lane < 16 && e + 16 + lane < runEnd) edn = __ldg(&g_edata[e + 16 + lane]);
#pragma unroll
        for (int i = 0; i < 4; i++) {
            int row = i * 4 + grow;
            int sk = __shfl_sync(0xffffffffu, edc.x, row);
            cp_async16(shW + row * 128 + ((gchk ^ (row & 7)) * 16),
                       &g_h14[sk * 8 + gchk], (e + row < runEnd) ? 16 : 0);
        }
        cp_commit();

        int b = 0;
        for (int c = e; c < runEnd; c += 16) {
            int2 ed2 = make_int2(0, 0);
            if (lane < 16 && c + 32 + lane < runEnd) ed2 = __ldg(&g_edata[c + 32 + lane]);

            // prefetch next tile into other buffer
#pragma unroll
            for (int i = 0; i < 4; i++) {
                int row = i * 4 + grow;
                int sk = __shfl_sync(0xffffffffu, edn.x, row);
                cp_async16(shW + (u32)(b ^ 1) * 2048 + row * 128 + ((gchk ^ (row & 7)) * 16),
                           &g_h14[sk * 8 + gchk], (c + 16 + row < runEnd) ? 16 : 0);
            }
            cp_commit();
            cp_wait1();
            __syncwarp();

            // ---- compute: C[4 nb][4 regs], 4 k-steps x (3-term split) ----
            float C00=0,C01=0,C02=0,C03=0, C10=0,C11=0,C12=0,C13=0;
            float C20=0,C21=0,C22=0,C23=0, C30=0,C31=0,C32=0,C33=0;
            const char* sb = sbase + b * 2048;
#pragma unroll
            for (int kb = 0; kb < 4; kb++) {
                int c0 = ((kb * 2)     ^ gr) * 16 + tig * 4;   // swizzled chunk for k..k+3
                int c1 = ((kb * 2 + 1) ^ gr) * 16 + tig * 4;   // for k+4..k+7
                float a0f = *(const float*)(sb + gr * 128 + c0);
                float a1f = *(const float*)(sb + (gr + 8) * 128 + c0);
                float a2f = *(const float*)(sb + gr * 128 + c1);
                float a3f = *(const float*)(sb + (gr + 8) * 128 + c1);
                u32 ah0 = cvt_tf32(a0f), ah1 = cvt_tf32(a1f);
                u32 ah2 = cvt_tf32(a2f), ah3 = cvt_tf32(a3f);
                u32 al0 = cvt_tf32(a0f - __uint_as_float(ah0));
                u32 al1 = cvt_tf32(a1f - __uint_as_float(ah1));
                u32 al2 = cvt_tf32(a2f - __uint_as_float(ah2));
                u32 al3 = cvt_tf32(a3f - __uint_as_float(ah3));
                mma_tf32(C00,C01,C02,C03, ah0,ah1,ah2,ah3, bhi[kb][0][0], bhi[kb][0][1]);
                mma_tf32(C10,C11,C12,C13, ah0,ah1,ah2,ah3, bhi[kb][1][0], bhi[kb][1][1]);
                mma_tf32(C20,C21,C22,C23, ah0,ah1,ah2,ah3, bhi[kb][2][0], bhi[kb][2][1]);
                mma_tf32(C30,C31,C32,C33, ah0,ah1,ah2,ah3, bhi[kb][3][0], bhi[kb][3][1]);
                mma_tf32(C00,C01,C02,C03, ah0,ah1,ah2,ah3, blo[kb][0][0], blo[kb][0][1]);
                mma_tf32(C10,C11,C12,C13, ah0,ah1,ah2,ah3, blo[kb][1][0], blo[kb][1][1]);
                mma_tf32(C20,C21,C22,C23, ah0,ah1,ah2,ah3, blo[kb][2][0], blo[kb][2][1]);
                mma_tf32(C30,C31,C32,C33, ah0,ah1,ah2,ah3, blo[kb][3][0], blo[kb][3][1]);
                mma_tf32(C00,C01,C02,C03, al0,al1,al2,al3, bhi[kb][0][0], bhi[kb][0][1]);
                mma_tf32(C10,C11,C12,C13, al0,al1,al2,al3, bhi[kb][1][0], bhi[kb][1][1]);
                mma_tf32(C20,C21,C22,C23, al0,al1,al2,al3, bhi[kb][2][0], bhi[kb][2][1]);
                mma_tf32(C30,C31,C32,C33, al0,al1,al2,al3, bhi[kb][3][0], bhi[kb][3][1]);
            }

            // ---- scatter: permuted h2 columns, 4 x red4 per tile ----
            int dA = __shfl_sync(0xffffffffu, edc.y, gr);
            int dB = __shfl_sync(0xffffffffu, edc.y, gr + 8);
            float* pA = (float*)g_h2 + (size_t)dA * DIM + tig * 8;
            float* pB = (float*)g_h2 + (size_t)dB * DIM + tig * 8;
            red4(pA,     C00, C01, C10, C11);   // row gr,   perm pos tig*8+0..3
            red4(pA + 4, C20, C21, C30, C31);   // row gr,   perm pos tig*8+4..7
            red4(pB,     C02, C03, C12, C13);   // row gr+8
            red4(pB + 4, C22, C23, C32, C33);
            edc = edn; edn = ed2; b ^= 1;
        }
        e = runEnd;
    }
}

// Final: out[v] = relu(h2perm[v] + b2) @ W3 + b3.  Reads h2 through the inverse
// column permutation; RESETS h2 row and (block 0) the rel counters after use.
__global__ void k_final(const float* __restrict__ W3, const float* __restrict__ b2,
                        const float* __restrict__ b3, float* __restrict__ out, int N) {
    __shared__ float sW[DIM * DIM];
    __shared__ float sb2[DIM];
    __shared__ float sb3[DIM];
    int t = threadIdx.x;
    for (int i = t; i < DIM * DIM; i += blockDim.x) sW[i] = W3[i];
    if (t < DIM) { sb2[t] = b2[t]; sb3[t] = b3[t]; }
    if (blockIdx.x == 0 && t < NRELS) { g_relHist[t] = 0; g_relCur[t] = 0; }
    __syncthreads();
    int lane = t & 31;
    int wpb = blockDim.x >> 5;
    int pos = ((lane & 7) >> 1) * 8 + (lane >> 3) * 2 + (lane & 1);  // perm of col=lane
    float* h2 = (float*)g_h2;
    for (int v = blockIdx.x * wpb + (t >> 5); v < N; v += gridDim.x * wpb) {
        float h = fmaxf(h2[v * DIM + pos] + sb2[lane], 0.0f);
        h2[v * DIM + lane] = 0.0f;                      // reset for next pass
        float acc = sb3[lane];
#pragma unroll
        for (int i = 0; i < DIM; i++) {
            float hi = __shfl_sync(0xffffffffu, h, i);
            acc += hi * sW[i * DIM + lane];
        }
        out[v * DIM + lane] = acc;
    }
}

// ---------------- launch ----------------
extern "C" void kernel_launch(void* const* d_in, const int* in_sizes, int n_in,
                              void* d_out, int out_size) {
    const int* src = (const int*)d_in[0];
    const int* dst = (const int*)d_in[1];
    const int* et  = (const int*)d_in[2];
    int base = (n_in > 3 && in_sizes[3] == 1) ? 4 : 3;
    const float* W1 = (const float*)d_in[base + 0];
    const float* b1 = (const float*)d_in[base + 1];
    const float* W2 = (const float*)d_in[base + 2];
    const float* b2 = (const float*)d_in[base + 3];
    const float* W3 = (const float*)d_in[base + 4];
    const float* b3 = (const float*)d_in[base + 5];

    int E = in_sizes[0];
    int N = out_size / DIM;
    float* out = (float*)d_out;

    int edgeBlocks4 = (E / 4 + 255) / 256 + 1;
    k_hist<<<edgeBlocks4, 256>>>(dst, et, E);          // launch 0
    k_scatter<<<edgeBlocks4, 256>>>(src, dst, et, E);  // launch 1

    int nodeBlocks = (N + 7) / 8;
    k_layer1<<<nodeBlocks, 256>>>(W1, b1, N);          // launch 2

    const int nWarps = 1776;   // 148 SMs x 3 blocks x 4 warps, one wave
    k_layer2<<<nWarps / 4, 128>>>(W2, E, nWarps);      // launch 3 (profiled slot)

    k_final<<<nodeBlocks, 256>>>(W3, b2, b3, out, N);  // launch 4
}

// round 12
// speedup vs baseline: 1.2477x; 1.2477x over previous
#include <cuda_runtime.h>

#define NRELS 19
#define CPAD  20
#define DIM   32
#define MAXN  100000
#define MAXE  1600000

typedef unsigned int u32;

// ---------------- static scratch (zero-init; each consumer kernel resets
// what it read, so every graph replay starts pristine) ----------------------
static __device__ int4   g_cnt4[MAXN * (CPAD / 4)];   // (node,rel) counts
static __device__ float4 g_h14[MAXN * (DIM / 4)];     // layer-1 activations
static __device__ float4 g_h2[MAXN * (DIM / 4)];      // layer-2 accumulator (perm cols)
static __device__ int2   g_edata[MAXE];               // relation-bucketed (src,dst)
static __device__ int    g_relHist[NRELS];
static __device__ int    g_relCur[NRELS];

// ---------------- helpers ----------------
__device__ __forceinline__ void red4(float* p, float a, float b, float c, float d) {
    asm volatile("red.global.add.v4.f32 [%0], {%1, %2, %3, %4};"
                 :: "l"(p), "f"(a), "f"(b), "f"(c), "f"(d) : "memory");
}
__device__ __forceinline__ u32 smem_u32(const void* p) {
    return (u32)__cvta_generic_to_shared(p);
}
__device__ __forceinline__ void cp_async16(u32 dst, const void* src, int srcsize) {
    asm volatile("cp.async.cg.shared.global [%0], [%1], 16, %2;"
                 :: "r"(dst), "l"(src), "r"(srcsize));
}
__device__ __forceinline__ void cp_commit() { asm volatile("cp.async.commit_group;"); }
__device__ __forceinline__ void cp_wait1()  { asm volatile("cp.async.wait_group 1;"); }
__device__ __forceinline__ void cp_wait0()  { asm volatile("cp.async.wait_group 0;"); }
// pack {lo, hi} floats into bf16x2 (element0 = lo)
__device__ __forceinline__ u32 bf16x2(float lo, float hi) {
    u32 r; asm("cvt.rn.bf16x2.f32 %0, %1, %2;" : "=r"(r) : "f"(hi), "f"(lo)); return r;
}
// residual of a float2 after removing its bf16x2 hi part
__device__ __forceinline__ u32 bf16x2_lo(float x, float y, u32 hi) {
    float lx = x - __uint_as_float(hi << 16);
    float ly = y - __uint_as_float(hi & 0xFFFF0000u);
    return bf16x2(lx, ly);
}
// m16n8k16 bf16 MMA, fp32 accumulate in place.
__device__ __forceinline__ void mma_bf16(float& c0, float& c1, float& c2, float& c3,
                                         u32 a0, u32 a1, u32 a2, u32 a3,
                                         u32 b0, u32 b1) {
    asm volatile("mma.sync.aligned.m16n8k16.row.col.f32.bf16.bf16.f32 "
                 "{%0,%1,%2,%3}, {%4,%5,%6,%7}, {%8,%9}, {%0,%1,%2,%3};"
                 : "+f"(c0), "+f"(c1), "+f"(c2), "+f"(c3)
                 : "r"(a0), "r"(a1), "r"(a2), "r"(a3), "r"(b0), "r"(b1));
}

// ---------------- kernels (order: hist, scatter, layer1, LAYER2, final) ----

__global__ void k_hist(const int* __restrict__ dst, const int* __restrict__ et, int E) {
    __shared__ int sh[NRELS];
    if (threadIdx.x < NRELS) sh[threadIdx.x] = 0;
    __syncthreads();
    int* cnt = (int*)g_cnt4;
    int e0 = (blockIdx.x * blockDim.x + threadIdx.x) * 4;
    if (e0 + 3 < E) {
        int4 d4 = *(const int4*)&dst[e0];
        int4 r4 = *(const int4*)&et[e0];
        atomicAdd(&cnt[d4.x * CPAD + r4.x], 1);
        atomicAdd(&cnt[d4.y * CPAD + r4.y], 1);
        atomicAdd(&cnt[d4.z * CPAD + r4.z], 1);
        atomicAdd(&cnt[d4.w * CPAD + r4.w], 1);
        atomicAdd(&sh[r4.x], 1); atomicAdd(&sh[r4.y], 1);
        atomicAdd(&sh[r4.z], 1); atomicAdd(&sh[r4.w], 1);
    } else {
        for (int e = e0; e < E; e++) {
            int r = et[e];
            atomicAdd(&cnt[dst[e] * CPAD + r], 1);
            atomicAdd(&sh[r], 1);
        }
    }
    __syncthreads();
    if (threadIdx.x < NRELS) atomicAdd(&g_relHist[threadIdx.x], sh[threadIdx.x]);
}

__global__ void k_scatter(const int* __restrict__ src, const int* __restrict__ dst,
                          const int* __restrict__ et, int E) {
    __shared__ int sOff[NRELS];
    __shared__ int shCnt[NRELS];
    __shared__ int shBase[NRELS];
    int t = threadIdx.x;
    if (t < NRELS) {
        shCnt[t] = 0;
        int s = 0;
#pragma unroll
        for (int q = 0; q < NRELS; q++) {
            if (q == t) sOff[t] = s;
            s += g_relHist[q];
        }
    }
    __syncthreads();
    int e0 = (blockIdx.x * blockDim.x + t) * 4;
    int r[4], s[4], d[4], lp[4];
    int cnt = 0;
    if (e0 + 3 < E) {
        int4 s4 = *(const int4*)&src[e0];
        int4 d4 = *(const int4*)&dst[e0];
        int4 r4 = *(const int4*)&et[e0];
        s[0]=s4.x; s[1]=s4.y; s[2]=s4.z; s[3]=s4.w;
        d[0]=d4.x; d[1]=d4.y; d[2]=d4.z; d[3]=d4.w;
        r[0]=r4.x; r[1]=r4.y; r[2]=r4.z; r[3]=r4.w;
        cnt = 4;
    } else {
        for (int e = e0; e < E; e++) {
            s[cnt]=src[e]; d[cnt]=dst[e]; r[cnt]=et[e]; cnt++;
        }
    }
    for (int k = 0; k < cnt; k++) lp[k] = atomicAdd(&shCnt[r[k]], 1);
    __syncthreads();
    if (t < NRELS) shBase[t] = sOff[t] + atomicAdd(&g_relCur[t], shCnt[t]);
    __syncthreads();
    for (int k = 0; k < cnt; k++)
        g_edata[shBase[r[k]] + lp[k]] = make_int2(s[k], d[k]);
}

// Layer 1; also RESETS cnt rows to zero after reading.
__global__ void k_layer1(const float* __restrict__ W1, const float* __restrict__ b1, int N) {
    __shared__ float sW[NRELS * DIM];
    __shared__ float sb[DIM];
    int t = threadIdx.x;
    for (int i = t; i < NRELS * DIM; i += blockDim.x) sW[i] = W1[i];
    if (t < DIM) sb[t] = b1[t];
    __syncthreads();
    int lane = t & 31;
    int wpb = blockDim.x >> 5;
    float* h1 = (float*)g_h14;
    for (int v = blockIdx.x * wpb + (t >> 5); v < N; v += gridDim.x * wpb) {
        int4* crow = &g_cnt4[v * (CPAD / 4)];
        int c[CPAD];
#pragma unroll
        for (int q = 0; q < CPAD / 4; q++) {
            int4 cc = __ldg(&crow[q]);
            c[q * 4 + 0] = cc.x; c[q * 4 + 1] = cc.y;
            c[q * 4 + 2] = cc.z; c[q * 4 + 3] = cc.w;
        }
        float acc = sb[lane];
#pragma unroll
        for (int r = 0; r < NRELS; r++)
            acc += (float)c[r] * sW[r * DIM + lane];
        h1[v * DIM + lane] = fmaxf(acc, 0.0f);
        if (lane < CPAD / 4) crow[lane] = make_int4(0, 0, 0, 0);
    }
}

// Layer 2 (hot): bf16 tensor tiles.  Per warp, 16 edges per tile:
//   D[16 x 32] += A[16 x 32] (gathered h1 rows) @ W2[rel] (32 x 32)
// via mma.m16n8k16.bf16 with 2x2 hi/lo split, 3 terms (AhiBhi+AhiBlo+AloBhi,
// dropped AloBlo ~2^-16): 24 MMAs/tile, W fragments 32 regs (vs 64 tf32),
// occupancy 5 blocks/SM.
//   - A: cp.async16 gather into XOR-swizzled smem (double-buffered); padded
//     edges zero-filled -> exact 0 contributions.
//   - C scatter: h2 stored with column perm pos=((c&7)>>1)*8+(c>>3)*2+(c&1)
//     so each lane's C regs form contiguous 16B groups -> 4 red4/tile.
__global__ void __launch_bounds__(128, 5) k_layer2(const float* __restrict__ W2,
                                                   int E, int nWarps) {
    __shared__ float shh[4][2][512];    // [warp][buf][16 rows x 32 floats] 16KB
    __shared__ int sOff[NRELS + 1];
    int t = threadIdx.x;
    if (t == 0) {
        int s = 0;
        for (int q = 0; q < NRELS; q++) { sOff[q] = s; s += g_relHist[q]; }
        sOff[NRELS] = s;
    }
    __syncthreads();
    int lane = t & 31;
    int warp = t >> 5;
    int gr   = lane >> 2;      // fragment group row (0..7)
    int tig  = lane & 3;       // thread-in-group
    int grow = lane >> 3;      // gather row-in-quad (0..3)
    int gchk = lane & 7;       // gather 16B chunk within 128B row
    u32 shW = smem_u32(&shh[warp][0][0]);
    const char* sbase = (const char*)&shh[warp][0][0];

    int gw = blockIdx.x * 4 + warp;
    if (gw >= nWarps) return;
    int e    = (int)(((long long)gw * E) / nWarps);
    int eEnd = (int)(((long long)(gw + 1) * E) / nWarps);

    int r = 0;
    while (e < eEnd) {
        while (sOff[r + 1] <= e) r++;
        int runEnd = min(eEnd, sOff[r + 1]);
        if (e >= runEnd) continue;

        // ---- W2[r] bf16 hi/lo fragments, register-resident (32 regs) ----
        // b0 = {W[k0][n0], W[k0+1][n0]}, b1 = {W[k0+8][n0], W[k0+9][n0]},
        // k0 = ks*16 + 2*tig, n0 = nb*8 + gr.
        const float* Wr = W2 + r * DIM * DIM;
        u32 bhi[2][4][2], blo[2][4][2];
#pragma unroll
        for (int ks = 0; ks < 2; ks++)
#pragma unroll
            for (int nb = 0; nb < 4; nb++) {
                int k0 = ks * 16 + 2 * tig, n0 = nb * 8 + gr;
                float w00 = __ldg(&Wr[k0 * DIM + n0]);
                float w01 = __ldg(&Wr[(k0 + 1) * DIM + n0]);
                float w10 = __ldg(&Wr[(k0 + 8) * DIM + n0]);
                float w11 = __ldg(&Wr[(k0 + 9) * DIM + n0]);
                u32 h0 = bf16x2(w00, w01);
                u32 h1 = bf16x2(w10, w11);
                bhi[ks][nb][0] = h0;
                bhi[ks][nb][1] = h1;
                blo[ks][nb][0] = bf16x2_lo(w00, w01, h0);
                blo[ks][nb][1] = bf16x2_lo(w10, w11, h1);
            }

        cp_wait0();
        __syncwarp();

        // ---- prolog: edata 2 tiles deep; gather tile 0 into buf 0 ----
        int2 edc = make_int2(0, 0), edn = make_int2(0, 0);
        if (lane < 16 && e + lane < runEnd) edc = __ldg(&g_edata[e + lane]);
        if (lane < 16 && e + 16 + lane < runEnd) edn = __ldg(&g_edata[e + 16 + lane]);
#pragma unroll
        for (int i = 0; i < 4; i++) {
            int row = i * 4 + grow;
            int sk = __shfl_sync(0xffffffffu, edc.x, row);
            cp_async16(shW + row * 128 + ((gchk ^ (row & 7)) * 16),
                       &g_h14[sk * 8 + gchk], (e + row < runEnd) ? 16 : 0);
        }
        cp_commit();

        int b = 0;
        for (int c = e; c < runEnd; c += 16) {
            int2 ed2 = make_int2(0, 0);
            if (lane < 16 && c + 32 + lane < runEnd) ed2 = __ldg(&g_edata[c + 32 + lane]);

            // prefetch next tile into other buffer
#pragma unroll
            for (int i = 0; i < 4; i++) {
                int row = i * 4 + grow;
                int sk = __shfl_sync(0xffffffffu, edn.x, row);
                cp_async16(shW + (u32)(b ^ 1) * 2048 + row * 128 + ((gchk ^ (row & 7)) * 16),
                           &g_h14[sk * 8 + gchk], (c + 16 + row < runEnd) ? 16 : 0);
            }
            cp_commit();
            cp_wait1();
            __syncwarp();

            // ---- compute: 2 ksteps x (A convert + 12 MMAs) ----
            float C00=0,C01=0,C02=0,C03=0, C10=0,C11=0,C12=0,C13=0;
            float C20=0,C21=0,C22=0,C23=0, C30=0,C31=0,C32=0,C33=0;
            const char* sb = sbase + b * 2048;
#pragma unroll
            for (int ks = 0; ks < 2; ks++) {
                // A frag a0={row gr, k 2tig..2tig+1}, a1={row gr+8, same},
                // a2/a3 = +8 in k.  bytes: 8*tig + 64*ks (+32 for a2/a3).
                int ch0 = 4 * ks + (tig >> 1);
                int off = (tig & 1) * 8;
                const char* rp0 = sb + gr * 128;
                const char* rp1 = sb + (gr + 8) * 128;
                float2 f0 = *(const float2*)(rp0 + ((ch0 ^ gr) * 16) + off);
                float2 f1 = *(const float2*)(rp1 + ((ch0 ^ gr) * 16) + off);
                float2 f2 = *(const float2*)(rp0 + (((ch0 + 2) ^ gr) * 16) + off);
                float2 f3 = *(const float2*)(rp1 + (((ch0 + 2) ^ gr) * 16) + off);
                u32 ah0 = bf16x2(f0.x, f0.y), ah1 = bf16x2(f1.x, f1.y);
                u32 ah2 = bf16x2(f2.x, f2.y), ah3 = bf16x2(f3.x, f3.y);
                u32 al0 = bf16x2_lo(f0.x, f0.y, ah0);
                u32 al1 = bf16x2_lo(f1.x, f1.y, ah1);
                u32 al2 = bf16x2_lo(f2.x, f2.y, ah2);
                u32 al3 = bf16x2_lo(f3.x, f3.y, ah3);
                mma_bf16(C00,C01,C02,C03, ah0,ah1,ah2,ah3, bhi[ks][0][0], bhi[ks][0][1]);
                mma_bf16(C10,C11,C12,C13, ah0,ah1,ah2,ah3, bhi[ks][1][0], bhi[ks][1][1]);
                mma_bf16(C20,C21,C22,C23, ah0,ah1,ah2,ah3, bhi[ks][2][0], bhi[ks][2][1]);
                mma_bf16(C30,C31,C32,C33, ah0,ah1,ah2,ah3, bhi[ks][3][0], bhi[ks][3][1]);
                mma_bf16(C00,C01,C02,C03, ah0,ah1,ah2,ah3, blo[ks][0][0], blo[ks][0][1]);
                mma_bf16(C10,C11,C12,C13, ah0,ah1,ah2,ah3, blo[ks][1][0], blo[ks][1][1]);
                mma_bf16(C20,C21,C22,C23, ah0,ah1,ah2,ah3, blo[ks][2][0], blo[ks][2][1]);
                mma_bf16(C30,C31,C32,C33, ah0,ah1,ah2,ah3, blo[ks][3][0], blo[ks][3][1]);
                mma_bf16(C00,C01,C02,C03, al0,al1,al2,al3, bhi[ks][0][0], bhi[ks][0][1]);
                mma_bf16(C10,C11,C12,C13, al0,al1,al2,al3, bhi[ks][1][0], bhi[ks][1][1]);
                mma_bf16(C20,C21,C22,C23, al0,al1,al2,al3, bhi[ks][2][0], bhi[ks][2][1]);
                mma_bf16(C30,C31,C32,C33, al0,al1,al2,al3, bhi[ks][3][0], bhi[ks][3][1]);
            }

            // ---- scatter: C cols nb*8+2tig+j -> perm pos tig*8 + nb*2 + j ----
            // lane covers rows gr (c0,c1) and gr+8 (c2,c3): 2 x 2 red4.
            int dA = __shfl_sync(0xffffffffu, edc.y, gr);
            int dB = __shfl_sync(0xffffffffu, edc.y, gr + 8);
            float* pA = (float*)g_h2 + (size_t)dA * DIM + tig * 8;
            float* pB = (float*)g_h2 + (size_t)dB * DIM + tig * 8;
            red4(pA,     C00, C01, C10, C11);
            red4(pA + 4, C20, C21, C30, C31);
            red4(pB,     C02, C03, C12, C13);
            red4(pB + 4, C22, C23, C32, C33);
            edc = edn; edn = ed2; b ^= 1;
        }
        e = runEnd;
    }
}

// Final: out[v] = relu(h2perm[v] + b2) @ W3 + b3; inverse perm read; resets
// h2 row and (block 0) the rel counters for the next graph replay.
__global__ void k_final(const float* __restrict__ W3, const float* __restrict__ b2,
                        const float* __restrict__ b3, float* __restrict__ out, int N) {
    __shared__ float sW[DIM * DIM];
    __shared__ float sb2[DIM];
    __shared__ float sb3[DIM];
    int t = threadIdx.x;
    for (int i = t; i < DIM * DIM; i += blockDim.x) sW[i] = W3[i];
    if (t < DIM) { sb2[t] = b2[t]; sb3[t] = b3[t]; }
    if (blockIdx.x == 0 && t < NRELS) { g_relHist[t] = 0; g_relCur[t] = 0; }
    __syncthreads();
    int lane = t & 31;
    int wpb = blockDim.x >> 5;
    int pos = ((lane & 7) >> 1) * 8 + (lane >> 3) * 2 + (lane & 1);
    float* h2 = (float*)g_h2;
    for (int v = blockIdx.x * wpb + (t >> 5); v < N; v += gridDim.x * wpb) {
        float h = fmaxf(h2[v * DIM + pos] + sb2[lane], 0.0f);
        h2[v * DIM + lane] = 0.0f;
        float acc = sb3[lane];
#pragma unroll
        for (int i = 0; i < DIM; i++) {
            float hi = __shfl_sync(0xffffffffu, h, i);
            acc += hi * sW[i * DIM + lane];
        }
        out[v * DIM + lane] = acc;
    }
}

// ---------------- launch ----------------
extern "C" void kernel_launch(void* const* d_in, const int* in_sizes, int n_in,
                              void* d_out, int out_size) {
    const int* src = (const int*)d_in[0];
    const int* dst = (const int*)d_in[1];
    const int* et  = (const int*)d_in[2];
    int base = (n_in > 3 && in_sizes[3] == 1) ? 4 : 3;
    const float* W1 = (const float*)d_in[base + 0];
    const float* b1 = (const float*)d_in[base + 1];
    const float* W2 = (const float*)d_in[base + 2];
    const float* b2 = (const float*)d_in[base + 3];
    const float* W3 = (const float*)d_in[base + 4];
    const float* b3 = (const float*)d_in[base + 5];

    int E = in_sizes[0];
    int N = out_size / DIM;
    float* out = (float*)d_out;

    int edgeBlocks4 = (E / 4 + 255) / 256 + 1;
    k_hist<<<edgeBlocks4, 256>>>(dst, et, E);          // launch 0
    k_scatter<<<edgeBlocks4, 256>>>(src, dst, et, E);  // launch 1

    int nodeBlocks = (N + 7) / 8;
    k_layer1<<<nodeBlocks, 256>>>(W1, b1, N);          // launch 2

    const int nWarps = 2960;   // 148 SMs x 5 blocks x 4 warps, one wave
    k_layer2<<<nWarps / 4, 128>>>(W2, E, nWarps);      // launch 3 (profiled slot)

    k_final<<<nodeBlocks, 256>>>(W3, b2, b3, out, N);  // launch 4
}